// round 11
// baseline (speedup 1.0000x reference)
#include <cuda_runtime.h>
#include <math.h>

#define BB 64
#define CC 32
#define HH 16
#define VV 4096
#define NMAX 16384
#define NCHK 64          // chunks of 64 codes

typedef unsigned long long u64;

// ---------------- scratch ----------------
__device__ float g_fhat[BB*CC*HH*HH];
__device__ float g_rest[NMAX*CC];
__device__ float g_esq[VV];          // holds -0.5*|e|^2
__device__ uint2 g_di[NMAX*64];      // point-major {val_bits, code_idx}
__device__ float g_wsT[4*9216];      // transposed weights [k][ci*9+pos][co]
__device__ float g_loss;

// ---------------- f32x2 helpers ----------------
__device__ __forceinline__ void fma2(u64& acc, u64 a, u64 b) {
    asm("fma.rn.f32x2 %0, %1, %2, %0;" : "+l"(acc) : "l"(a), "l"(b));
}
__device__ __forceinline__ u64 add2(u64 a, u64 b) {
    u64 r; asm("add.rn.f32x2 %0, %1, %2;" : "=l"(r) : "l"(a), "l"(b)); return r;
}
__device__ __forceinline__ u64 dup2(float v) {
    u64 r; asm("mov.b64 %0, {%1,%1};" : "=l"(r) : "f"(v)); return r;
}
__device__ __forceinline__ float2 upk2(u64 v) {
    float2 f; asm("mov.b64 {%0,%1}, %2;" : "=f"(f.x), "=f"(f.y) : "l"(v)); return f;
}

// ---------------- init ----------------
__global__ void k_init(const float* __restrict__ embed, const float* __restrict__ phi_w) {
    int i = blockIdx.x*blockDim.x + threadIdx.x;
    if (i < BB*CC*HH*HH) g_fhat[i] = 0.f;
    if (i == 0) g_loss = 0.f;
    if (i < VV) {
        const float4* e4 = (const float4*)(embed + i*32);
        float s = 0.f;
        #pragma unroll
        for (int q = 0; q < 8; q++) {
            float4 a = e4[q];
            s = fmaf(a.x, a.x, s); s = fmaf(a.y, a.y, s);
            s = fmaf(a.z, a.z, s); s = fmaf(a.w, a.w, s);
        }
        g_esq[i] = -0.5f * s;
    }
    if (i < 4*9216) {
        int co = i & 31;
        int u  = (i >> 5) % 288;
        int k  = i / 9216;
        int dx = u % 3, dy = (u/3) % 3, ci = u/9;
        g_wsT[i] = phi_w[k*9216 + ((co*32 + ci)*9 + dy*3 + dx)];
    }
}

// ---------------- pool: warp per (n,c) for big windows ----------------
__global__ void k_pool_w(const float* __restrict__ f, int pn, int N) {
    int gw = (blockIdx.x*blockDim.x + threadIdx.x) >> 5;
    int lane = threadIdx.x & 31;
    if (gw >= N*CC) return;
    int c = gw & 31, n = gw >> 5;
    int pp = pn*pn;
    int b = n / pp, r = n % pp, i = r / pn, j = r % pn;
    int wh = HH / pn;
    int npx = wh*wh;
    int s0 = i*wh, s1 = j*wh;
    const float* fb = f      + ((b*CC + c) << 8);
    const float* hb = g_fhat + ((b*CC + c) << 8);
    float s = 0.f;
    for (int p = lane; p < npx; p += 32) {
        int h = s0 + p / wh, w = s1 + p % wh;
        s += fb[h*16 + w] - hb[h*16 + w];
    }
    #pragma unroll
    for (int o = 16; o > 0; o >>= 1) s += __shfl_down_sync(0xffffffffu, s, o);
    if (lane == 0) g_rest[n*32 + c] = s / (float)npx;
}

// ---------------- pool: thread per (n,c) ----------------
__global__ void k_pool(const float* __restrict__ f, int pn, int N) {
    int t = blockIdx.x*blockDim.x + threadIdx.x;
    if (t >= N*CC) return;
    int c = t & 31, n = t >> 5;
    int pp = pn*pn;
    int b = n / pp, r = n % pp, i = r / pn, j = r % pn;
    int s0 = (i*HH)/pn,  e0 = ((i+1)*HH + pn - 1)/pn;
    int s1 = (j*HH)/pn,  e1 = ((j+1)*HH + pn - 1)/pn;
    const float* fb = f      + ((b*CC + c) << 8);
    const float* hb = g_fhat + ((b*CC + c) << 8);
    float s = 0.f;
    for (int h = s0; h < e0; h++)
        for (int w = s1; w < e1; w++)
            s += fb[h*16 + w] - hb[h*16 + w];
    g_rest[n*32 + c] = s / (float)((e0 - s0) * (e1 - s1));
}

// ---------------- dist: 64-code chunk, VPT vectors/thread, f32x2 ----------------
template<int VPT>
__global__ __launch_bounds__(128) void k_dist(const float* __restrict__ embed, int N) {
    __shared__ ulonglong2 es[64*8];
    __shared__ float ess[64];
    int ck = blockIdx.y;
    int t  = threadIdx.x;
    {
        const float4* src = (const float4*)(embed + (ck*64)*32);
        float4* dst = (float4*)es;
        #pragma unroll
        for (int q = t; q < 512; q += 128) dst[q] = src[q];
        if (t < 64) ess[t] = g_esq[ck*64 + t];
    }
    int nn[VPT]; bool vv[VPT];
    u64 x[VPT][16];
    #pragma unroll
    for (int s = 0; s < VPT; s++) {
        nn[s] = blockIdx.x*(128*VPT) + s*128 + t;
        vv[s] = (nn[s] < N);
        #pragma unroll
        for (int q = 0; q < 16; q++) x[s][q] = 0ull;
        if (vv[s]) {
            const ulonglong2* xp = (const ulonglong2*)(g_rest + nn[s]*32);
            #pragma unroll
            for (int q = 0; q < 8; q++) { ulonglong2 a = xp[q]; x[s][2*q] = a.x; x[s][2*q+1] = a.y; }
        }
    }
    __syncthreads();
    if (!vv[0]) return;
    float bv[VPT]; int bi[VPT];
    #pragma unroll
    for (int s = 0; s < VPT; s++) { bv[s] = -3.4e38f; bi[s] = 0; }
    #pragma unroll 2
    for (int v = 0; v < 64; v++) {
        u64 a0[VPT], a1[VPT];
        #pragma unroll
        for (int s = 0; s < VPT; s++) { a0[s] = 0ull; a1[s] = 0ull; }
        #pragma unroll
        for (int q = 0; q < 8; q++) {
            ulonglong2 e = es[v*8 + q];
            #pragma unroll
            for (int s = 0; s < VPT; s++) {
                fma2(a0[s], x[s][2*q],   e.x);
                fma2(a1[s], x[s][2*q+1], e.y);
            }
        }
        float esv = ess[v];
        #pragma unroll
        for (int s = 0; s < VPT; s++) {
            float2 f2 = upk2(add2(a0[s], a1[s]));
            float val = (f2.x + f2.y) + esv;
            if (val > bv[s]) { bv[s] = val; bi[s] = v; }
        }
    }
    #pragma unroll
    for (int s = 0; s < VPT; s++)
        if (vv[s]) g_di[nn[s]*64 + ck] =
            make_uint2(__float_as_uint(bv[s]), (unsigned)(ck*64 + bi[s]));
}

// ---------------- gather(warp-argmin) + upsample + Phi conv + f_hat + loss ----------------
// grid = 512 (8 two-row bands per image), block = 256
// smem: hq/ws union 9216 + hs 2304 + red 256 = 11776 floats = 47104 B
__global__ __launch_bounds__(256) void k_phi(
    const float* __restrict__ f, const float* __restrict__ embed,
    const float* __restrict__ phi_b,
    int pn, int kidx)
{
    extern __shared__ float sm[];
    float* hq  = sm;            // [local_p][c] gathered codes (phase A)
    float* ws  = sm;            // [pos][co] weights (phase B, aliases hq)
    float* hs  = sm + 9216;     // 2304 floats: [c][4][18] zero padded
    float* red = hs + 2304;     // 256
    int t  = threadIdx.x;
    int b  = blockIdx.x >> 3;
    int r0 = (blockIdx.x & 7) * 2;
    int np = pn*pn;
    int warp = t >> 5, lane = t & 31;

    // needed source row range for this band
    float sc = pn * 0.0625f;
    int ylo = (int)floorf((r0 - 0.5f)*sc - 0.5f);
    int yhi = (int)floorf((r0 + 2.5f)*sc - 0.5f) + 1;
    ylo = min(max(ylo, 0), pn-1);
    yhi = min(max(yhi, 0), pn-1);
    int cnt = (yhi - ylo + 1) * pn;

    // phase A: warp per point — reduce 64 chunks, gather code into hq
    for (int pt = warp; pt < cnt; pt += 8) {
        int p = (ylo + pt / pn) * pn + (pt % pn);
        int base = (b*np + p) * 64;
        uint2 c0 = g_di[base + lane];
        uint2 c1 = g_di[base + 32 + lane];
        float v0 = __uint_as_float(c0.x); int i0 = (int)c0.y;
        float v1 = __uint_as_float(c1.x); int i1 = (int)c1.y;
        if (v1 > v0) { v0 = v1; i0 = i1; }   // tie keeps lower chunk
        #pragma unroll
        for (int o = 16; o > 0; o >>= 1) {
            float vo = __shfl_down_sync(0xffffffffu, v0, o);
            int   io = __shfl_down_sync(0xffffffffu, i0, o);
            if (vo > v0 || (vo == v0 && io < i0)) { v0 = vo; i0 = io; }
        }
        i0 = __shfl_sync(0xffffffffu, i0, 0);
        hq[pt*32 + lane] = embed[i0*32 + lane];
    }
    // zero hs
    #pragma unroll
    for (int q = t; q < 2304; q += 256) hs[q] = 0.f;
    __syncthreads();

    // bilinear upsample rows r0-1..r0+2 -> hs local rows 0..3
    if (t < 64) {
        int lr = t >> 4;       // 0..3
        int x  = t & 15;
        int gy = r0 - 1 + lr;
        if (gy >= 0 && gy < 16) {
            float sy = (gy + 0.5f) * sc - 0.5f;
            float y0f = floorf(sy);
            float fy = sy - y0f;
            int y0 = (int)y0f, y1i = y0 + 1;
            y0  = min(max(y0, 0), pn-1);
            y1i = min(max(y1i, 0), pn-1);
            float sx = (x + 0.5f) * sc - 0.5f;
            float x0f = floorf(sx);
            float fx = sx - x0f;
            int xx0 = (int)x0f, xx1 = xx0 + 1;
            xx0 = min(max(xx0, 0), pn-1);
            xx1 = min(max(xx1, 0), pn-1);
            float w00 = (1.f-fy)*(1.f-fx), w01 = (1.f-fy)*fx;
            float w10 = fy*(1.f-fx),       w11 = fy*fx;
            const float* p00 = hq + ((y0 -ylo)*pn + xx0)*32;
            const float* p01 = hq + ((y0 -ylo)*pn + xx1)*32;
            const float* p10 = hq + ((y1i-ylo)*pn + xx0)*32;
            const float* p11 = hq + ((y1i-ylo)*pn + xx1)*32;
            for (int c = 0; c < 32; c++) {
                float v = w00*p00[c] + w01*p01[c] + w10*p10[c] + w11*p11[c];
                hs[(c*4 + lr)*18 + (x+1)] = v;
            }
        }
    }
    __syncthreads();

    // phase B: weights into smem (overwrites hq)
    {
        const float4* src = (const float4*)(g_wsT + kidx*9216);
        float4* dst = (float4*)ws;
        #pragma unroll
        for (int q = t; q < 2304; q += 256) dst[q] = src[q];
    }
    __syncthreads();

    // conv3x3: 1 px, 4 co per thread; hv scalar load + alu-pipe dup
    int px = t & 31;
    int ty = px >> 4, tx = px & 15;     // ty 0..1
    int co0 = (t >> 5) * 4;             // 0,4,...,28
    u64 acc0 = *(const u64*)(phi_b + kidx*32 + co0);
    u64 acc1 = *(const u64*)(phi_b + kidx*32 + co0 + 2);
    #pragma unroll 4
    for (int ci = 0; ci < 32; ci++) {
        #pragma unroll
        for (int dy = 0; dy < 3; dy++) {
            #pragma unroll
            for (int dx = 0; dx < 3; dx++) {
                u64 hv2 = dup2(hs[(ci*4 + ty+dy)*18 + (tx+dx)]);
                const ulonglong2* w2 = (const ulonglong2*)(ws + ((ci*3+dy)*3+dx)*32 + co0);
                ulonglong2 w = *w2;
                fma2(acc0, hv2, w.x);
                fma2(acc1, hv2, w.y);
            }
        }
    }
    int y = r0 + ty;
    float sse = 0.f;
    float2 a0 = upk2(acc0), a1 = upk2(acc1);
    float cv[4] = {a0.x, a0.y, a1.x, a1.y};
    #pragma unroll
    for (int q = 0; q < 4; q++) {
        int co = co0 + q;
        float hu = hs[(co*4 + ty+1)*18 + (tx+1)];
        float hphi = 0.5f*hu + 0.5f*cv[q];
        int off = ((b*32 + co) << 8) + y*16 + tx;
        float fh = g_fhat[off] + hphi;
        g_fhat[off] = fh;
        float d = fh - f[off];
        sse = fmaf(d, d, sse);
    }
    red[t] = sse;
    __syncthreads();
    for (int s = 128; s > 0; s >>= 1) {
        if (t < s) red[t] += red[t + s];
        __syncthreads();
    }
    if (t == 0) atomicAdd(&g_loss, red[0]);
}

// ---------------- output ----------------
__global__ void k_out(float* __restrict__ out, int out_size) {
    int i = blockIdx.x*blockDim.x + threadIdx.x;
    if (i < out_size && i < BB*CC*HH*HH) out[i] = g_fhat[i];
    if (i == 0) {
        float lv = g_loss * (1.25f / (8.0f * 524288.0f));
        if (out_size > BB*CC*HH*HH) out[BB*CC*HH*HH] = lv;
        else if (out_size == 1)     out[0] = lv;
    }
}

// ---------------- launch ----------------
extern "C" void kernel_launch(void* const* d_in, const int* in_sizes, int n_in,
                              void* d_out, int out_size) {
    const float* f     = (const float*)d_in[0];
    const float* embed = (const float*)d_in[1];
    const float* phi_w = (const float*)d_in[2];
    const float* phi_b = (const float*)d_in[3];
    (void)in_sizes; (void)n_in;

    const int smem_phi = (9216 + 2304 + 256) * 4;  // 47104 B
    cudaFuncSetAttribute(k_phi, cudaFuncAttributeMaxDynamicSharedMemorySize, smem_phi);

    static const int pns[8] = {1, 2, 4, 6, 8, 10, 13, 16};
    static const int kk [8] = {0, 0, 1, 1, 2, 2, 3, 3};

    k_init<<<2048, 256>>>(embed, phi_w);

    for (int si = 0; si < 8; si++) {
        int pn = pns[si];
        int N  = BB * pn * pn;
        if (pn <= 2) {
            int nwarp = N * CC;
            k_pool_w<<<(nwarp*32 + 255)/256, 256>>>(f, pn, N);
        } else {
            k_pool<<<(N*CC + 255)/256, 256>>>(f, pn, N);
        }
        if (pn >= 8) {
            dim3 g1((N + 511)/512, NCHK);
            k_dist<4><<<g1, 128>>>(embed, N);
        } else {
            dim3 g1((N + 255)/256, NCHK);
            k_dist<2><<<g1, 128>>>(embed, N);
        }
        k_phi<<<512, 256, smem_phi>>>(f, embed, phi_b, pn, kk[si]);
    }
    k_out<<<2049, 256>>>((float*)d_out, out_size);
}

// round 12
// speedup vs baseline: 1.1386x; 1.1386x over previous
#include <cuda_runtime.h>
#include <math.h>

#define BB 64
#define CC 32
#define HH 16
#define VV 4096
#define NMAX 16384
#define NCHK 64          // chunks of 64 codes

typedef unsigned long long u64;

// ---------------- scratch ----------------
__device__ float g_fhat[BB*CC*HH*HH];
__device__ float g_rest[NMAX*CC];
__device__ float g_esq[VV];          // holds -0.5*|e|^2
__device__ uint2 g_di[NMAX*64];      // point-major {val_bits, code_idx}
__device__ float g_wsT[4*9216];      // transposed weights [k][ci*9+pos][co]
__device__ float g_loss;

// ---------------- f32x2 helpers ----------------
__device__ __forceinline__ void fma2(u64& acc, u64 a, u64 b) {
    asm("fma.rn.f32x2 %0, %1, %2, %0;" : "+l"(acc) : "l"(a), "l"(b));
}
__device__ __forceinline__ u64 add2(u64 a, u64 b) {
    u64 r; asm("add.rn.f32x2 %0, %1, %2;" : "=l"(r) : "l"(a), "l"(b)); return r;
}
__device__ __forceinline__ u64 dup2(float v) {
    u64 r; asm("mov.b64 %0, {%1,%1};" : "=l"(r) : "f"(v)); return r;
}
__device__ __forceinline__ float2 upk2(u64 v) {
    float2 f; asm("mov.b64 {%0,%1}, %2;" : "=f"(f.x), "=f"(f.y) : "l"(v)); return f;
}

// ---------------- init ----------------
__global__ void k_init(const float* __restrict__ embed, const float* __restrict__ phi_w) {
    int i = blockIdx.x*blockDim.x + threadIdx.x;
    if (i < BB*CC*HH*HH) g_fhat[i] = 0.f;
    if (i == 0) g_loss = 0.f;
    if (i < VV) {
        const float4* e4 = (const float4*)(embed + i*32);
        float s = 0.f;
        #pragma unroll
        for (int q = 0; q < 8; q++) {
            float4 a = e4[q];
            s = fmaf(a.x, a.x, s); s = fmaf(a.y, a.y, s);
            s = fmaf(a.z, a.z, s); s = fmaf(a.w, a.w, s);
        }
        g_esq[i] = -0.5f * s;
    }
    if (i < 4*9216) {
        int co = i & 31;
        int u  = (i >> 5) % 288;
        int k  = i / 9216;
        int dx = u % 3, dy = (u/3) % 3, ci = u/9;
        g_wsT[i] = phi_w[k*9216 + ((co*32 + ci)*9 + dy*3 + dx)];
    }
}

// ---------------- pool: warp per (n,c) for big windows ----------------
__global__ void k_pool_w(const float* __restrict__ f, int pn, int N) {
    int gw = (blockIdx.x*blockDim.x + threadIdx.x) >> 5;
    int lane = threadIdx.x & 31;
    if (gw >= N*CC) return;
    int c = gw & 31, n = gw >> 5;
    int pp = pn*pn;
    int b = n / pp, r = n % pp, i = r / pn, j = r % pn;
    int wh = HH / pn;
    int npx = wh*wh;
    int s0 = i*wh, s1 = j*wh;
    const float* fb = f      + ((b*CC + c) << 8);
    const float* hb = g_fhat + ((b*CC + c) << 8);
    float s = 0.f;
    for (int p = lane; p < npx; p += 32) {
        int h = s0 + p / wh, w = s1 + p % wh;
        s += fb[h*16 + w] - hb[h*16 + w];
    }
    #pragma unroll
    for (int o = 16; o > 0; o >>= 1) s += __shfl_down_sync(0xffffffffu, s, o);
    if (lane == 0) g_rest[n*32 + c] = s / (float)npx;
}

// ---------------- pool: thread per (n,c) ----------------
__global__ void k_pool(const float* __restrict__ f, int pn, int N) {
    int t = blockIdx.x*blockDim.x + threadIdx.x;
    if (t >= N*CC) return;
    int c = t & 31, n = t >> 5;
    int pp = pn*pn;
    int b = n / pp, r = n % pp, i = r / pn, j = r % pn;
    int s0 = (i*HH)/pn,  e0 = ((i+1)*HH + pn - 1)/pn;
    int s1 = (j*HH)/pn,  e1 = ((j+1)*HH + pn - 1)/pn;
    const float* fb = f      + ((b*CC + c) << 8);
    const float* hb = g_fhat + ((b*CC + c) << 8);
    float s = 0.f;
    for (int h = s0; h < e0; h++)
        for (int w = s1; w < e1; w++)
            s += fb[h*16 + w] - hb[h*16 + w];
    g_rest[n*32 + c] = s / (float)((e0 - s0) * (e1 - s1));
}

// ---------------- dist: 64-code chunk, VPT vectors/thread, f32x2 ----------------
template<int VPT>
__global__ __launch_bounds__(128) void k_dist(const float* __restrict__ embed, int N) {
    __shared__ ulonglong2 es[64*8];
    __shared__ float ess[64];
    int ck = blockIdx.y;
    int t  = threadIdx.x;
    {
        const float4* src = (const float4*)(embed + (ck*64)*32);
        float4* dst = (float4*)es;
        #pragma unroll
        for (int q = t; q < 512; q += 128) dst[q] = src[q];
        if (t < 64) ess[t] = g_esq[ck*64 + t];
    }
    int nn[VPT]; bool vv[VPT];
    u64 x[VPT][16];
    #pragma unroll
    for (int s = 0; s < VPT; s++) {
        nn[s] = blockIdx.x*(128*VPT) + s*128 + t;
        vv[s] = (nn[s] < N);
        #pragma unroll
        for (int q = 0; q < 16; q++) x[s][q] = 0ull;
        if (vv[s]) {
            const ulonglong2* xp = (const ulonglong2*)(g_rest + nn[s]*32);
            #pragma unroll
            for (int q = 0; q < 8; q++) { ulonglong2 a = xp[q]; x[s][2*q] = a.x; x[s][2*q+1] = a.y; }
        }
    }
    __syncthreads();
    if (!vv[0]) return;
    float bv[VPT]; int bi[VPT];
    #pragma unroll
    for (int s = 0; s < VPT; s++) { bv[s] = -3.4e38f; bi[s] = 0; }
    #pragma unroll 2
    for (int v = 0; v < 64; v++) {
        u64 a0[VPT], a1[VPT];
        #pragma unroll
        for (int s = 0; s < VPT; s++) { a0[s] = 0ull; a1[s] = 0ull; }
        #pragma unroll
        for (int q = 0; q < 8; q++) {
            ulonglong2 e = es[v*8 + q];
            #pragma unroll
            for (int s = 0; s < VPT; s++) {
                fma2(a0[s], x[s][2*q],   e.x);
                fma2(a1[s], x[s][2*q+1], e.y);
            }
        }
        float esv = ess[v];
        #pragma unroll
        for (int s = 0; s < VPT; s++) {
            float2 f2 = upk2(add2(a0[s], a1[s]));
            float val = (f2.x + f2.y) + esv;
            if (val > bv[s]) { bv[s] = val; bi[s] = v; }
        }
    }
    #pragma unroll
    for (int s = 0; s < VPT; s++)
        if (vv[s]) g_di[nn[s]*64 + ck] =
            make_uint2(__float_as_uint(bv[s]), (unsigned)(ck*64 + bi[s]));
}

// ---------------- gather(warp-argmin) + upsample + Phi conv + f_hat + loss ----------------
// grid = 256 (4 four-row bands per image), block = 256
// thread: 2 px (x-pair) x 4 co.  cell = t&31: ry=cell>>3 (0..3), xp=cell&7; co0=(t>>5)*4
// smem: hq/ws union 9216 + hs 3648 ([c][6][19]) + red 256 = 13120 floats = 52480 B
__global__ __launch_bounds__(256) void k_phi(
    const float* __restrict__ f, const float* __restrict__ embed,
    const float* __restrict__ phi_b,
    int pn, int kidx)
{
    extern __shared__ float sm[];
    float* hq  = sm;            // [local_p][c] gathered codes (phase A)
    float* ws  = sm;            // [pos][co] weights (phase B, aliases hq)
    float* hs  = sm + 9216;     // 3648 floats: [c][6][19] zero padded
    float* red = hs + 3648;     // 256
    int t  = threadIdx.x;
    int b  = blockIdx.x >> 2;
    int r0 = (blockIdx.x & 3) * 4;
    int np = pn*pn;
    int warp = t >> 5, lane = t & 31;

    // needed source row range for this band (rows r0-1 .. r0+4 of output)
    float sc = pn * 0.0625f;
    int ylo = (int)floorf((r0 - 0.5f)*sc - 0.5f);
    int yhi = (int)floorf((r0 + 4.5f)*sc - 0.5f) + 1;
    ylo = min(max(ylo, 0), pn-1);
    yhi = min(max(yhi, 0), pn-1);
    int cnt = (yhi - ylo + 1) * pn;     // <= 96

    // phase A: warp per point — reduce 64 chunks, gather code into hq
    for (int pt = warp; pt < cnt; pt += 8) {
        int p = (ylo + pt / pn) * pn + (pt % pn);
        int base = (b*np + p) * 64;
        uint2 c0 = g_di[base + lane];
        uint2 c1 = g_di[base + 32 + lane];
        float v0 = __uint_as_float(c0.x); int i0 = (int)c0.y;
        float v1 = __uint_as_float(c1.x); int i1 = (int)c1.y;
        if (v1 > v0) { v0 = v1; i0 = i1; }   // tie keeps lower chunk
        #pragma unroll
        for (int o = 16; o > 0; o >>= 1) {
            float vo = __shfl_down_sync(0xffffffffu, v0, o);
            int   io = __shfl_down_sync(0xffffffffu, i0, o);
            if (vo > v0 || (vo == v0 && io < i0)) { v0 = vo; i0 = io; }
        }
        i0 = __shfl_sync(0xffffffffu, i0, 0);
        hq[pt*32 + lane] = embed[i0*32 + lane];
    }
    // zero hs
    #pragma unroll
    for (int q = t; q < 3648; q += 256) hs[q] = 0.f;
    __syncthreads();

    // bilinear upsample rows r0-1..r0+4 -> hs local rows 0..5, cols 1..16
    if (t < 96) {
        int lr = t >> 4;       // 0..5
        int x  = t & 15;
        int gy = r0 - 1 + lr;
        if (gy >= 0 && gy < 16) {
            float sy = (gy + 0.5f) * sc - 0.5f;
            float y0f = floorf(sy);
            float fy = sy - y0f;
            int y0 = (int)y0f, y1i = y0 + 1;
            y0  = min(max(y0, 0), pn-1);
            y1i = min(max(y1i, 0), pn-1);
            float sx = (x + 0.5f) * sc - 0.5f;
            float x0f = floorf(sx);
            float fx = sx - x0f;
            int xx0 = (int)x0f, xx1 = xx0 + 1;
            xx0 = min(max(xx0, 0), pn-1);
            xx1 = min(max(xx1, 0), pn-1);
            float w00 = (1.f-fy)*(1.f-fx), w01 = (1.f-fy)*fx;
            float w10 = fy*(1.f-fx),       w11 = fy*fx;
            const float* p00 = hq + ((y0 -ylo)*pn + xx0)*32;
            const float* p01 = hq + ((y0 -ylo)*pn + xx1)*32;
            const float* p10 = hq + ((y1i-ylo)*pn + xx0)*32;
            const float* p11 = hq + ((y1i-ylo)*pn + xx1)*32;
            for (int c = 0; c < 32; c++) {
                float v = w00*p00[c] + w01*p01[c] + w10*p10[c] + w11*p11[c];
                hs[(c*6 + lr)*19 + (x+1)] = v;
            }
        }
    }
    __syncthreads();

    // phase B: weights into smem (overwrites hq)
    {
        const float4* src = (const float4*)(g_wsT + kidx*9216);
        float4* dst = (float4*)ws;
        #pragma unroll
        for (int q = t; q < 2304; q += 256) dst[q] = src[q];
    }
    __syncthreads();

    // conv3x3: 2 px x 4 co per thread, register-blocked hv
    int cell = t & 31;
    int ry = cell >> 3, xp = cell & 7;
    int tx0 = xp * 2;
    int co0 = (t >> 5) * 4;
    u64 bias0 = *(const u64*)(phi_b + kidx*32 + co0);
    u64 bias1 = *(const u64*)(phi_b + kidx*32 + co0 + 2);
    u64 pa0 = bias0, pa1 = bias1;      // px0 accums
    u64 pb0 = bias0, pb1 = bias1;      // px1 accums
    #pragma unroll 4
    for (int ci = 0; ci < 32; ci++) {
        #pragma unroll
        for (int dy = 0; dy < 3; dy++) {
            const float* hrow = hs + (ci*6 + ry + dy)*19 + tx0;
            u64 h0 = dup2(hrow[0]);
            u64 h1 = dup2(hrow[1]);
            u64 h2 = dup2(hrow[2]);
            u64 h3 = dup2(hrow[3]);
            const ulonglong2* wrow = (const ulonglong2*)(ws + ((ci*3+dy)*3)*32 + co0);
            ulonglong2 w0 = wrow[0];              // dx=0
            ulonglong2 w1 = *(const ulonglong2*)((const float*)wrow + 32);   // dx=1
            ulonglong2 w2 = *(const ulonglong2*)((const float*)wrow + 64);   // dx=2
            fma2(pa0, h0, w0.x); fma2(pa1, h0, w0.y);
            fma2(pb0, h1, w0.x); fma2(pb1, h1, w0.y);
            fma2(pa0, h1, w1.x); fma2(pa1, h1, w1.y);
            fma2(pb0, h2, w1.x); fma2(pb1, h2, w1.y);
            fma2(pa0, h2, w2.x); fma2(pa1, h2, w2.y);
            fma2(pb0, h3, w2.x); fma2(pb1, h3, w2.y);
        }
    }
    int y = r0 + ry;
    float sse = 0.f;
    float2 a0 = upk2(pa0), a1 = upk2(pa1), b0 = upk2(pb0), b1 = upk2(pb1);
    float cva[4] = {a0.x, a0.y, a1.x, a1.y};
    float cvb[4] = {b0.x, b0.y, b1.x, b1.y};
    #pragma unroll
    for (int q = 0; q < 4; q++) {
        int co = co0 + q;
        const float* hurow = hs + (co*6 + ry+1)*19 + tx0 + 1;
        int off = ((b*32 + co) << 8) + y*16 + tx0;
        // px0
        {
            float hphi = 0.5f*hurow[0] + 0.5f*cva[q];
            float fh = g_fhat[off] + hphi;
            g_fhat[off] = fh;
            float d = fh - f[off];
            sse = fmaf(d, d, sse);
        }
        // px1
        {
            float hphi = 0.5f*hurow[1] + 0.5f*cvb[q];
            float fh = g_fhat[off+1] + hphi;
            g_fhat[off+1] = fh;
            float d = fh - f[off+1];
            sse = fmaf(d, d, sse);
        }
    }
    red[t] = sse;
    __syncthreads();
    for (int s = 128; s > 0; s >>= 1) {
        if (t < s) red[t] += red[t + s];
        __syncthreads();
    }
    if (t == 0) atomicAdd(&g_loss, red[0]);
}

// ---------------- output ----------------
__global__ void k_out(float* __restrict__ out, int out_size) {
    int i = blockIdx.x*blockDim.x + threadIdx.x;
    if (i < out_size && i < BB*CC*HH*HH) out[i] = g_fhat[i];
    if (i == 0) {
        float lv = g_loss * (1.25f / (8.0f * 524288.0f));
        if (out_size > BB*CC*HH*HH) out[BB*CC*HH*HH] = lv;
        else if (out_size == 1)     out[0] = lv;
    }
}

// ---------------- launch ----------------
extern "C" void kernel_launch(void* const* d_in, const int* in_sizes, int n_in,
                              void* d_out, int out_size) {
    const float* f     = (const float*)d_in[0];
    const float* embed = (const float*)d_in[1];
    const float* phi_w = (const float*)d_in[2];
    const float* phi_b = (const float*)d_in[3];
    (void)in_sizes; (void)n_in;

    const int smem_phi = (9216 + 3648 + 256) * 4;  // 52480 B
    cudaFuncSetAttribute(k_phi, cudaFuncAttributeMaxDynamicSharedMemorySize, smem_phi);

    static const int pns[8] = {1, 2, 4, 6, 8, 10, 13, 16};
    static const int kk [8] = {0, 0, 1, 1, 2, 2, 3, 3};

    k_init<<<2048, 256>>>(embed, phi_w);

    for (int si = 0; si < 8; si++) {
        int pn = pns[si];
        int N  = BB * pn * pn;
        if (pn <= 2) {
            int nwarp = N * CC;
            k_pool_w<<<(nwarp*32 + 255)/256, 256>>>(f, pn, N);
        } else {
            k_pool<<<(N*CC + 255)/256, 256>>>(f, pn, N);
        }
        if (pn >= 8) {
            dim3 g1((N + 511)/512, NCHK);
            k_dist<4><<<g1, 128>>>(embed, N);
        } else {
            dim3 g1((N + 255)/256, NCHK);
            k_dist<2><<<g1, 128>>>(embed, N);
        }
        k_phi<<<256, 256, smem_phi>>>(f, embed, phi_b, pn, kk[si]);
    }
    k_out<<<2049, 256>>>((float*)d_out, out_size);
}

// round 15
// speedup vs baseline: 1.1642x; 1.0224x over previous
#include <cuda_runtime.h>
#include <math.h>

#define BB 64
#define CC 32
#define HH 16
#define VV 4096
#define NMAX 16384
#define NCHK 64          // chunks of 64 codes

typedef unsigned long long u64;

// ---------------- scratch ----------------
__device__ float g_fhat[BB*CC*HH*HH];
__device__ float g_rest[NMAX*CC];
__device__ float g_esq[VV];          // holds -0.5*|e|^2
__device__ uint2 g_di[NMAX*64];      // point-major {val_bits, code_idx}
__device__ float g_wsT[4*9216];      // transposed weights [k][ci*9+pos][co]
__device__ float g_loss;

// ---------------- f32x2 helpers ----------------
__device__ __forceinline__ void fma2(u64& acc, u64 a, u64 b) {
    asm("fma.rn.f32x2 %0, %1, %2, %0;" : "+l"(acc) : "l"(a), "l"(b));
}
__device__ __forceinline__ u64 add2(u64 a, u64 b) {
    u64 r; asm("add.rn.f32x2 %0, %1, %2;" : "=l"(r) : "l"(a), "l"(b)); return r;
}
__device__ __forceinline__ u64 dup2(float v) {
    u64 r; asm("mov.b64 %0, {%1,%1};" : "=l"(r) : "f"(v)); return r;
}
__device__ __forceinline__ u64 pklo(float v) {           // (v, 0)
    u64 r; asm("{ .reg .f32 z; mov.f32 z, 0f00000000; mov.b64 %0, {%1, z}; }"
               : "=l"(r) : "f"(v)); return r;
}
__device__ __forceinline__ float2 upk2(u64 v) {
    float2 f; asm("mov.b64 {%0,%1}, %2;" : "=f"(f.x), "=f"(f.y) : "l"(v)); return f;
}

// ---------------- init ----------------
__global__ void k_init(const float* __restrict__ embed, const float* __restrict__ phi_w) {
    int i = blockIdx.x*blockDim.x + threadIdx.x;
    if (i < BB*CC*HH*HH) g_fhat[i] = 0.f;
    if (i == 0) g_loss = 0.f;
    if (i < VV) {
        const float4* e4 = (const float4*)(embed + i*32);
        float s = 0.f;
        #pragma unroll
        for (int q = 0; q < 8; q++) {
            float4 a = e4[q];
            s = fmaf(a.x, a.x, s); s = fmaf(a.y, a.y, s);
            s = fmaf(a.z, a.z, s); s = fmaf(a.w, a.w, s);
        }
        g_esq[i] = -0.5f * s;
    }
    if (i < 4*9216) {
        int co = i & 31;
        int u  = (i >> 5) % 288;
        int k  = i / 9216;
        int dx = u % 3, dy = (u/3) % 3, ci = u/9;
        g_wsT[i] = phi_w[k*9216 + ((co*32 + ci)*9 + dy*3 + dx)];
    }
}

// ---------------- pool: warp per (n,c) for big windows ----------------
__global__ void k_pool_w(const float* __restrict__ f, int pn, int N) {
    int gw = (blockIdx.x*blockDim.x + threadIdx.x) >> 5;
    int lane = threadIdx.x & 31;
    if (gw >= N*CC) return;
    int c = gw & 31, n = gw >> 5;
    int pp = pn*pn;
    int b = n / pp, r = n % pp, i = r / pn, j = r % pn;
    int wh = HH / pn;
    int npx = wh*wh;
    int s0 = i*wh, s1 = j*wh;
    const float* fb = f      + ((b*CC + c) << 8);
    const float* hb = g_fhat + ((b*CC + c) << 8);
    float s = 0.f;
    for (int p = lane; p < npx; p += 32) {
        int h = s0 + p / wh, w = s1 + p % wh;
        s += fb[h*16 + w] - hb[h*16 + w];
    }
    #pragma unroll
    for (int o = 16; o > 0; o >>= 1) s += __shfl_down_sync(0xffffffffu, s, o);
    if (lane == 0) g_rest[n*32 + c] = s / (float)npx;
}

// ---------------- pool: thread per (n,c) ----------------
__global__ void k_pool(const float* __restrict__ f, int pn, int N) {
    int t = blockIdx.x*blockDim.x + threadIdx.x;
    if (t >= N*CC) return;
    int c = t & 31, n = t >> 5;
    int pp = pn*pn;
    int b = n / pp, r = n % pp, i = r / pn, j = r % pn;
    int s0 = (i*HH)/pn,  e0 = ((i+1)*HH + pn - 1)/pn;
    int s1 = (j*HH)/pn,  e1 = ((j+1)*HH + pn - 1)/pn;
    const float* fb = f      + ((b*CC + c) << 8);
    const float* hb = g_fhat + ((b*CC + c) << 8);
    float s = 0.f;
    for (int h = s0; h < e0; h++)
        for (int w = s1; w < e1; w++)
            s += fb[h*16 + w] - hb[h*16 + w];
    g_rest[n*32 + c] = s / (float)((e0 - s0) * (e1 - s1));
}

// ---------------- dist: 64-code chunk, VPT vectors/thread, f32x2 ----------------
template<int VPT>
__global__ __launch_bounds__(128) void k_dist(const float* __restrict__ embed, int N) {
    __shared__ ulonglong2 es[64*8];
    __shared__ float ess[64];
    int ck = blockIdx.y;
    int t  = threadIdx.x;
    {
        const float4* src = (const float4*)(embed + (ck*64)*32);
        float4* dst = (float4*)es;
        #pragma unroll
        for (int q = t; q < 512; q += 128) dst[q] = src[q];
        if (t < 64) ess[t] = g_esq[ck*64 + t];
    }
    int nn[VPT]; bool vv[VPT];
    u64 x[VPT][16];
    #pragma unroll
    for (int s = 0; s < VPT; s++) {
        nn[s] = blockIdx.x*(128*VPT) + s*128 + t;
        vv[s] = (nn[s] < N);
        #pragma unroll
        for (int q = 0; q < 16; q++) x[s][q] = 0ull;
        if (vv[s]) {
            const ulonglong2* xp = (const ulonglong2*)(g_rest + nn[s]*32);
            #pragma unroll
            for (int q = 0; q < 8; q++) { ulonglong2 a = xp[q]; x[s][2*q] = a.x; x[s][2*q+1] = a.y; }
        }
    }
    __syncthreads();
    if (!vv[0]) return;
    float bv[VPT]; int bi[VPT];
    #pragma unroll
    for (int s = 0; s < VPT; s++) { bv[s] = -3.4e38f; bi[s] = 0; }
    #pragma unroll 4
    for (int v = 0; v < 64; v++) {
        float esv = ess[v];
        u64 e0v = pklo(esv);           // (esv, 0) — alu pipe, folds norm into accum
        u64 a0[VPT], a1[VPT];
        #pragma unroll
        for (int s = 0; s < VPT; s++) { a0[s] = e0v; a1[s] = 0ull; }
        #pragma unroll
        for (int q = 0; q < 8; q++) {
            ulonglong2 e = es[v*8 + q];
            #pragma unroll
            for (int s = 0; s < VPT; s++) {
                fma2(a0[s], x[s][2*q],   e.x);
                fma2(a1[s], x[s][2*q+1], e.y);
            }
        }
        #pragma unroll
        for (int s = 0; s < VPT; s++) {
            float2 f2 = upk2(add2(a0[s], a1[s]));
            float val = f2.x + f2.y;
            if (val > bv[s]) { bv[s] = val; bi[s] = v; }
        }
    }
    #pragma unroll
    for (int s = 0; s < VPT; s++)
        if (vv[s]) g_di[nn[s]*64 + ck] =
            make_uint2(__float_as_uint(bv[s]), (unsigned)(ck*64 + bi[s]));
}

// ---------------- gather(warp-argmin) + upsample + Phi conv + f_hat + loss ----------------
// grid = 256 (4 four-row bands per image), block = 256
// thread: 2 px (x-pair) x 4 co.
__global__ __launch_bounds__(256) void k_phi(
    const float* __restrict__ f, const float* __restrict__ embed,
    const float* __restrict__ phi_b,
    int pn, int kidx)
{
    extern __shared__ float sm[];
    float* hq  = sm;            // [local_p][c] gathered codes (phase A)
    float* ws  = sm;            // [pos][co] weights (phase B, aliases hq)
    float* hs  = sm + 9216;     // 3648 floats: [c][6][19] zero padded
    float* red = hs + 3648;     // 256
    int t  = threadIdx.x;
    int b  = blockIdx.x >> 2;
    int r0 = (blockIdx.x & 3) * 4;
    int np = pn*pn;
    int warp = t >> 5, lane = t & 31;

    float sc = pn * 0.0625f;
    int ylo = (int)floorf((r0 - 0.5f)*sc - 0.5f);
    int yhi = (int)floorf((r0 + 4.5f)*sc - 0.5f) + 1;
    ylo = min(max(ylo, 0), pn-1);
    yhi = min(max(yhi, 0), pn-1);
    int cnt = (yhi - ylo + 1) * pn;     // <= 96

    // phase A: warp per point — reduce 64 chunks, gather code into hq
    for (int pt = warp; pt < cnt; pt += 8) {
        int p = (ylo + pt / pn) * pn + (pt % pn);
        int base = (b*np + p) * 64;
        uint2 c0 = g_di[base + lane];
        uint2 c1 = g_di[base + 32 + lane];
        float v0 = __uint_as_float(c0.x); int i0 = (int)c0.y;
        float v1 = __uint_as_float(c1.x); int i1 = (int)c1.y;
        if (v1 > v0) { v0 = v1; i0 = i1; }   // tie keeps lower chunk
        #pragma unroll
        for (int o = 16; o > 0; o >>= 1) {
            float vo = __shfl_down_sync(0xffffffffu, v0, o);
            int   io = __shfl_down_sync(0xffffffffu, i0, o);
            if (vo > v0 || (vo == v0 && io < i0)) { v0 = vo; i0 = io; }
        }
        i0 = __shfl_sync(0xffffffffu, i0, 0);
        hq[pt*32 + lane] = embed[i0*32 + lane];
    }
    #pragma unroll
    for (int q = t; q < 3648; q += 256) hs[q] = 0.f;
    __syncthreads();

    // bilinear upsample rows r0-1..r0+4 -> hs local rows 0..5, cols 1..16
    if (t < 96) {
        int lr = t >> 4;       // 0..5
        int x  = t & 15;
        int gy = r0 - 1 + lr;
        if (gy >= 0 && gy < 16) {
            float sy = (gy + 0.5f) * sc - 0.5f;
            float y0f = floorf(sy);
            float fy = sy - y0f;
            int y0 = (int)y0f, y1i = y0 + 1;
            y0  = min(max(y0, 0), pn-1);
            y1i = min(max(y1i, 0), pn-1);
            float sx = (x + 0.5f) * sc - 0.5f;
            float x0f = floorf(sx);
            float fx = sx - x0f;
            int xx0 = (int)x0f, xx1 = xx0 + 1;
            xx0 = min(max(xx0, 0), pn-1);
            xx1 = min(max(xx1, 0), pn-1);
            float w00 = (1.f-fy)*(1.f-fx), w01 = (1.f-fy)*fx;
            float w10 = fy*(1.f-fx),       w11 = fy*fx;
            const float* p00 = hq + ((y0 -ylo)*pn + xx0)*32;
            const float* p01 = hq + ((y0 -ylo)*pn + xx1)*32;
            const float* p10 = hq + ((y1i-ylo)*pn + xx0)*32;
            const float* p11 = hq + ((y1i-ylo)*pn + xx1)*32;
            for (int c = 0; c < 32; c++) {
                float v = w00*p00[c] + w01*p01[c] + w10*p10[c] + w11*p11[c];
                hs[(c*6 + lr)*19 + (x+1)] = v;
            }
        }
    }
    __syncthreads();

    // phase B: weights into smem (overwrites hq)
    {
        const float4* src = (const float4*)(g_wsT + kidx*9216);
        float4* dst = (float4*)ws;
        #pragma unroll
        for (int q = t; q < 2304; q += 256) dst[q] = src[q];
    }
    __syncthreads();

    // conv3x3: 2 px x 4 co per thread, register-blocked hv, deep unroll for ILP
    int cell = t & 31;
    int ry = cell >> 3, xp = cell & 7;
    int tx0 = xp * 2;
    int co0 = (t >> 5) * 4;
    u64 bias0 = *(const u64*)(phi_b + kidx*32 + co0);
    u64 bias1 = *(const u64*)(phi_b + kidx*32 + co0 + 2);
    u64 pa0 = bias0, pa1 = bias1;      // px0 accums
    u64 pb0 = bias0, pb1 = bias1;      // px1 accums
    #pragma unroll 8
    for (int ci = 0; ci < 32; ci++) {
        #pragma unroll
        for (int dy = 0; dy < 3; dy++) {
            const float* hrow = hs + (ci*6 + ry + dy)*19 + tx0;
            u64 h0 = dup2(hrow[0]);
            u64 h1 = dup2(hrow[1]);
            u64 h2 = dup2(hrow[2]);
            u64 h3 = dup2(hrow[3]);
            const float* wbase = ws + ((ci*3+dy)*3)*32 + co0;
            ulonglong2 w0 = *(const ulonglong2*)(wbase);
            ulonglong2 w1 = *(const ulonglong2*)(wbase + 32);
            ulonglong2 w2 = *(const ulonglong2*)(wbase + 64);
            fma2(pa0, h0, w0.x); fma2(pa1, h0, w0.y);
            fma2(pb0, h1, w0.x); fma2(pb1, h1, w0.y);
            fma2(pa0, h1, w1.x); fma2(pa1, h1, w1.y);
            fma2(pb0, h2, w1.x); fma2(pb1, h2, w1.y);
            fma2(pa0, h2, w2.x); fma2(pa1, h2, w2.y);
            fma2(pb0, h3, w2.x); fma2(pb1, h3, w2.y);
        }
    }
    int y = r0 + ry;
    float sse = 0.f;
    float2 a0 = upk2(pa0), a1 = upk2(pa1), b0 = upk2(pb0), b1 = upk2(pb1);
    float cva[4] = {a0.x, a0.y, a1.x, a1.y};
    float cvb[4] = {b0.x, b0.y, b1.x, b1.y};
    #pragma unroll
    for (int q = 0; q < 4; q++) {
        int co = co0 + q;
        const float* hurow = hs + (co*6 + ry+1)*19 + tx0 + 1;
        int off = ((b*32 + co) << 8) + y*16 + tx0;
        {
            float hphi = 0.5f*hurow[0] + 0.5f*cva[q];
            float fh = g_fhat[off] + hphi;
            g_fhat[off] = fh;
            float d = fh - f[off];
            sse = fmaf(d, d, sse);
        }
        {
            float hphi = 0.5f*hurow[1] + 0.5f*cvb[q];
            float fh = g_fhat[off+1] + hphi;
            g_fhat[off+1] = fh;
            float d = fh - f[off+1];
            sse = fmaf(d, d, sse);
        }
    }
    red[t] = sse;
    __syncthreads();
    for (int s = 128; s > 0; s >>= 1) {
        if (t < s) red[t] += red[t + s];
        __syncthreads();
    }
    if (t == 0) atomicAdd(&g_loss, red[0]);
}

// ---------------- output ----------------
__global__ void k_out(float* __restrict__ out, int out_size) {
    int i = blockIdx.x*blockDim.x + threadIdx.x;
    if (i < out_size && i < BB*CC*HH*HH) out[i] = g_fhat[i];
    if (i == 0) {
        float lv = g_loss * (1.25f / (8.0f * 524288.0f));
        if (out_size > BB*CC*HH*HH) out[BB*CC*HH*HH] = lv;
        else if (out_size == 1)     out[0] = lv;
    }
}

// ---------------- launch ----------------
extern "C" void kernel_launch(void* const* d_in, const int* in_sizes, int n_in,
                              void* d_out, int out_size) {
    const float* f     = (const float*)d_in[0];
    const float* embed = (const float*)d_in[1];
    const float* phi_w = (const float*)d_in[2];
    const float* phi_b = (const float*)d_in[3];
    (void)in_sizes; (void)n_in;

    const int smem_phi = (9216 + 3648 + 256) * 4;  // 52480 B
    cudaFuncSetAttribute(k_phi, cudaFuncAttributeMaxDynamicSharedMemorySize, smem_phi);

    static const int pns[8] = {1, 2, 4, 6, 8, 10, 13, 16};
    static const int kk [8] = {0, 0, 1, 1, 2, 2, 3, 3};

    k_init<<<2048, 256>>>(embed, phi_w);

    for (int si = 0; si < 8; si++) {
        int pn = pns[si];
        int N  = BB * pn * pn;
        if (pn <= 2) {
            int nwarp = N * CC;
            k_pool_w<<<(nwarp*32 + 255)/256, 256>>>(f, pn, N);
        } else {
            k_pool<<<(N*CC + 255)/256, 256>>>(f, pn, N);
        }
        if (pn >= 8) {
            dim3 g1((N + 511)/512, NCHK);
            k_dist<4><<<g1, 128>>>(embed, N);
        } else {
            dim3 g1((N + 255)/256, NCHK);
            k_dist<2><<<g1, 128>>>(embed, N);
        }
        k_phi<<<256, 256, smem_phi>>>(f, embed, phi_b, pn, kk[si]);
    }
    k_out<<<2049, 256>>>((float*)d_out, out_size);
}